// round 2
// baseline (speedup 1.0000x reference)
#include <cuda_runtime.h>
#include <cstdint>

#define NV     8192
#define NT     1000
#define UNITS  20
#define IND    12
#define NCOL   80
#define VPG    4            // vehicles per 80-thread group
#define VB     8            // vehicles per block
#define TPG    80
#define GPB    2
#define THREADS (GPB*TPG)   // 160
#define BLOCKS  (NV/VB)     // 1024

// output packing (flat concat in reference return order)
#define OUT_POS 0
#define OUT_LC  (NV*NT)
#define OUT_SPD (OUT_LC + NV*NT*3)
#define OUT_H   (OUT_SPD + NV)
#define OUT_C   (OUT_H + NV*UNITS)

typedef unsigned long long ull;

__device__ __forceinline__ ull pk(float x, float y) {
    ull r; asm("mov.b64 %0, {%1,%2};" : "=l"(r) : "f"(x), "f"(y)); return r;
}
__device__ __forceinline__ float2 unpk(ull v) {
    float2 f; asm("mov.b64 {%0,%1}, %2;" : "=f"(f.x), "=f"(f.y) : "l"(v)); return f;
}
__device__ __forceinline__ void ffma2(ull& d, ull a, ull b) {
    asm("fma.rn.f32x2 %0, %1, %2, %0;" : "+l"(d) : "l"(a), "l"(b));
}
__device__ __forceinline__ float sigf(float x) {
    return __fdividef(1.0f, 1.0f + __expf(-x));
}
__device__ __forceinline__ float tanh_ex(float x) {
    return fmaf(2.0f, sigf(2.0f * x), -1.0f);
}
__device__ __forceinline__ float nanfix(float v) { return (v == v) ? v : 1.0f; }

__device__ __forceinline__ void cpasync16(uint32_t dst, const void* src) {
    asm volatile("cp.async.cg.shared.global [%0], [%1], 16;" :: "r"(dst), "l"(src));
}
#define CP_COMMIT() asm volatile("cp.async.commit_group;")
#define CP_WAIT0()  asm volatile("cp.async.wait_group 0;")

__global__ void __launch_bounds__(THREADS, 6)
rnncf_kernel(const float* __restrict__ inp,        // (NV, NT, 12)
             const float* __restrict__ init_state, // (NV, 2)
             const float* __restrict__ h0,         // (NV, 20)
             const float* __restrict__ c0,         // (NV, 20)
             const float* __restrict__ Wk,         // (12, 80)
             const float* __restrict__ Wr,         // (20, 80)
             const float* __restrict__ bz,         // (80)
             const float* __restrict__ d2w,        // (20, 10)
             const float* __restrict__ d2b,        // (10)
             const float* __restrict__ lcw,        // (10, 3)
             const float* __restrict__ lcb,        // (3)
             const float* __restrict__ d1w,        // (10, 1)
             const float* __restrict__ d1b,        // (1)
             float* __restrict__ out)
{
    // xin[buf][v]: floats 0..11 = cur, 12..31 = h   (8 float4 per vehicle)
    __shared__ float4 xin[2][VB][8];
    __shared__ float  raws[2][VB][12];     // raw input prefetch (cp.async)
    __shared__ float  xs[VB][12];          // head activations (10 used)
    __shared__ float  s_spd[VB];
    __shared__ float  s_d2t[10][UNITS];    // d2w transposed [col][k]
    __shared__ float  s_d2b[10];
    __shared__ float  s_head[10][4];       // [m][q]: q<3 -> lcw col q, q=3 -> d1w
    __shared__ float  s_headb[4];

    const int tid = threadIdx.x;
    const int grp = tid / TPG;
    const int j   = tid % TPG;     // 0..79
    const int u   = j >> 2;        // unit 0..19
    const int g   = j & 3;         // gate 0=i 1=f 2=g 3=o
    const int col = g * UNITS + u; // weight-matrix column
    const int vbase0 = blockIdx.x * VB;
    const int lane = tid & 31;
    const int qb = lane & ~3;      // quad base lane

    // ---- static weights -> smem ----
    for (int i = tid; i < 200; i += THREADS) s_d2t[i % 10][i / 10] = d2w[i];
    if (tid < 10) s_d2b[tid] = d2b[tid];
    if (tid < 40) { int m = tid >> 2, q = tid & 3; s_head[m][q] = (q < 3) ? lcw[m * 3 + q] : d1w[m]; }
    if (tid < 4)  s_headb[tid] = (tid < 3) ? lcb[tid] : d1b[0];

    // ---- LSTM weight column (register-resident, 16 f32x2) ----
    ull w2[16];
    const float biasj = bz[col];
#pragma unroll
    for (int p = 0; p < 16; p++) {
        int k0 = 2 * p, k1 = 2 * p + 1;
        float wa = (k0 < IND) ? Wk[k0 * NCOL + col] : Wr[(k0 - IND) * NCOL + col];
        float wb = (k1 < IND) ? Wk[k1 * NCOL + col] : Wr[(k1 - IND) * NCOL + col];
        w2[p] = pk(wa, wb);
    }

    // ---- state init ----
    float c_reg[VPG];
#pragma unroll
    for (int v = 0; v < VPG; v++) c_reg[v] = 0.0f;
    float pos = 0.0f;

    // h0 -> xin[0] (160 threads cover VB*20 exactly)
    {
        int v = tid / UNITS, uu = tid % UNITS;
        ((float*)&xin[0][v][0])[12 + uu] = h0[(vbase0 + v) * UNITS + uu];
    }
    if (g == 0) {
#pragma unroll
        for (int vi = 0; vi < VPG; vi++)
            c_reg[vi] = c0[(vbase0 + grp * VPG + vi) * UNITS + u];
    }
    if (tid >= 80 && tid < 80 + VB) {
        const int ov = tid - 80;
        const int vg = vbase0 + ov;
        pos = init_state[vg * 2 + 0];
        s_spd[ov] = init_state[vg * 2 + 1];
        // raw(0) direct load, build cur(0)
        const float4* ip = (const float4*)(inp + (size_t)vg * NT * 12);
        float4 r0 = ip[0], r1 = ip[1], r2 = ip[2];
        float* cb = (float*)&xin[0][ov][0];
        const float ih = 0.01f, iv = 0.025f;
        cb[0]  = nanfix((r0.x - pos) * ih);
        cb[1]  = nanfix((r0.y - pos) * ih);
        cb[2]  = nanfix((r0.z - pos) * ih);
        cb[3]  = nanfix((pos - r0.w) * ih);
        cb[4]  = nanfix((pos - r1.x) * ih);
        cb[5]  = nanfix((pos - r1.y) * ih);
        cb[6]  = nanfix(r1.z * iv);
        cb[7]  = nanfix(r1.w * iv);
        cb[8]  = nanfix(r2.x * iv);
        cb[9]  = nanfix(r2.y * iv);
        cb[10] = nanfix(r2.z * iv);
        cb[11] = nanfix(r2.w * iv);
        // prefetch raw(1) -> raws[1]
        uint32_t d = (uint32_t)__cvta_generic_to_shared(&raws[1][ov][0]);
        const float* src = inp + ((size_t)vg * NT + 1) * 12;
        cpasync16(d, src); cpasync16(d + 16, src + 4); cpasync16(d + 32, src + 8);
        CP_COMMIT();
    }
    __syncthreads();

    for (int t = 0; t < NT; t++) {
        const int tb = t & 1;

        // ---- Phase A: LSTM matvec + gates + cell (all threads) ----
#pragma unroll
        for (int vi = 0; vi < VPG; vi++) {
            const int v = grp * VPG + vi;
            const float4* xr4 = &xin[tb][v][0];
            ull a0 = pk(biasj, 0.0f);
            ull a1 = pk(0.0f, 0.0f);
#pragma unroll
            for (int q = 0; q < 8; q += 2) {
                float4 A = xr4[q];
                ffma2(a0, pk(A.x, A.y), w2[2 * q]);
                ffma2(a0, pk(A.z, A.w), w2[2 * q + 1]);
                float4 B = xr4[q + 1];
                ffma2(a1, pk(B.x, B.y), w2[2 * q + 2]);
                ffma2(a1, pk(B.z, B.w), w2[2 * q + 3]);
            }
            float2 fa = unpk(a0), fb = unpk(a1);
            float z = (fa.x + fa.y) + (fb.x + fb.y);
            float a = (g == 2) ? tanh_ex(z) : sigf(z);
            // quad gate gather
            float si = __shfl_sync(0xFFFFFFFFu, a, qb + 0);
            float sf = __shfl_sync(0xFFFFFFFFu, a, qb + 1);
            float tg = __shfl_sync(0xFFFFFFFFu, a, qb + 2);
            float so = __shfl_sync(0xFFFFFFFFu, a, qb + 3);
            if (g == 0) {
                float cc = fmaf(sf, c_reg[vi], si * tg);
                c_reg[vi] = cc;
                ((float*)&xin[tb ^ 1][v][0])[12 + u] = so * tanh_ex(cc);
            }
        }
        __syncthreads();   // barrier 1: h(t) visible

        // ---- Phase B: head-x (80 thr) + cur(t+1)/pos/prefetch (8 thr) ----
        if (tid < 80) {
            const int xv = tid / 10, xc = tid % 10;
            const float4* hr = (const float4*)(((const float*)&xin[tb ^ 1][xv][0]) + 12);
            const float4* wr = (const float4*)&s_d2t[xc][0];
            ull a0 = pk(s_d2b[xc], 0.0f);
            ull a1 = pk(0.0f, 0.0f);
#pragma unroll
            for (int m = 0; m < 5; m++) {
                float4 H = hr[m], W = wr[m];
                ffma2((m & 1) ? a1 : a0, pk(H.x, H.y), pk(W.x, W.y));
                ffma2((m & 1) ? a1 : a0, pk(H.z, H.w), pk(W.z, W.w));
            }
            float2 fa = unpk(a0), fb = unpk(a1);
            xs[xv][xc] = fmaxf((fa.x + fa.y) + (fb.x + fb.y), 0.0f);
        } else if (tid < 80 + VB) {
            const int ov = tid - 80;
            const int vg = vbase0 + ov;
            CP_WAIT0();                        // raw(t+1) landed
            float spd = s_spd[ov];
            pos = fmaf(0.1f, spd, pos);        // pos(t+1) = reference pos output at t
            out[OUT_POS + (size_t)vg * NT + t] = pos;
            const float4* rw = (const float4*)&raws[(t + 1) & 1][ov][0];
            float4 r0 = rw[0], r1 = rw[1], r2 = rw[2];
            float* cb = (float*)&xin[tb ^ 1][ov][0];
            const float ih = 0.01f, iv = 0.025f;
            cb[0]  = nanfix((r0.x - pos) * ih);
            cb[1]  = nanfix((r0.y - pos) * ih);
            cb[2]  = nanfix((r0.z - pos) * ih);
            cb[3]  = nanfix((pos - r0.w) * ih);
            cb[4]  = nanfix((pos - r1.x) * ih);
            cb[5]  = nanfix((pos - r1.y) * ih);
            cb[6]  = nanfix(r1.z * iv);
            cb[7]  = nanfix(r1.w * iv);
            cb[8]  = nanfix(r2.x * iv);
            cb[9]  = nanfix(r2.y * iv);
            cb[10] = nanfix(r2.z * iv);
            cb[11] = nanfix(r2.w * iv);
            if (t + 2 < NT) {                  // prefetch raw(t+2)
                uint32_t d = (uint32_t)__cvta_generic_to_shared(&raws[t & 1][ov][0]);
                const float* src = inp + ((size_t)vg * NT + (t + 2)) * 12;
                cpasync16(d, src); cpasync16(d + 16, src + 4); cpasync16(d + 32, src + 8);
                CP_COMMIT();
            }
        }
        __syncthreads();   // barrier 2: xs + cur(t+1) visible

        // ---- Phase C: lc / acc / spd update (32 threads; no trailing barrier) ----
        if (tid < 4 * VB) {
            const int cv = tid >> 2, cq = tid & 3;
            const int vg = vbase0 + cv;
            float acc = s_headb[cq];
#pragma unroll
            for (int m = 0; m < 10; m++) acc = fmaf(xs[cv][m], s_head[m][cq], acc);
            if (cq < 3) {
                out[OUT_LC + ((size_t)vg * NT + t) * 3 + cq] = acc;
            } else {
                float a = fmaf(10.0f, acc, -6.0f);
                s_spd[cv] = fmaf(0.1f, a, s_spd[cv]);
            }
        }
        // next barrier-1 orders C(t) reads of xs vs B(t+1) writes
    }

    __syncthreads();
    // ---- finals ----
    if (tid < VB) out[OUT_SPD + vbase0 + tid] = s_spd[tid];
    {
        int v = tid / UNITS, uu = tid % UNITS;   // 160 threads cover VB*20
        out[OUT_H + (size_t)(vbase0 + v) * UNITS + uu] =
            ((float*)&xin[NT & 1][v][0])[12 + uu];
    }
    if (g == 0) {
#pragma unroll
        for (int vi = 0; vi < VPG; vi++) {
            int vg = vbase0 + grp * VPG + vi;
            out[OUT_C + (size_t)vg * UNITS + u] = c_reg[vi];
        }
    }
}

extern "C" void kernel_launch(void* const* d_in, const int* in_sizes, int n_in,
                              void* d_out, int out_size) {
    const float* inp        = (const float*)d_in[0];
    const float* init_state = (const float*)d_in[1];
    const float* h0         = (const float*)d_in[2];
    const float* c0         = (const float*)d_in[3];
    const float* Wk         = (const float*)d_in[4];
    const float* Wr         = (const float*)d_in[5];
    const float* bzv        = (const float*)d_in[6];
    const float* d2w        = (const float*)d_in[7];
    const float* d2b        = (const float*)d_in[8];
    const float* lcw        = (const float*)d_in[9];
    const float* lcb        = (const float*)d_in[10];
    const float* d1w        = (const float*)d_in[11];
    const float* d1b        = (const float*)d_in[12];
    float* out = (float*)d_out;

    rnncf_kernel<<<BLOCKS, THREADS>>>(inp, init_state, h0, c0, Wk, Wr, bzv,
                                      d2w, d2b, lcw, lcb, d1w, d1b, out);
}

// round 3
// speedup vs baseline: 1.0529x; 1.0529x over previous
#include <cuda_runtime.h>
#include <cstdint>

#define NV     8192
#define NT     1000
#define UNITS  20
#define IND    12
#define NCOL   80
#define VB     8            // vehicles per block
#define THREADS 160         // 4 groups of 40 threads; group serves 2 vehicles
#define BLOCKS (NV/VB)      // 1024

// output packing (flat concat in reference return order)
#define OUT_POS 0
#define OUT_LC  (NV*NT)
#define OUT_SPD (OUT_LC + NV*NT*3)
#define OUT_H   (OUT_SPD + NV)
#define OUT_C   (OUT_H + NV*UNITS)

typedef unsigned long long ull;

__device__ __forceinline__ ull pk(float x, float y) {
    ull r; asm("mov.b64 %0, {%1,%2};" : "=l"(r) : "f"(x), "f"(y)); return r;
}
__device__ __forceinline__ float2 unpk(ull v) {
    float2 f; asm("mov.b64 {%0,%1}, %2;" : "=f"(f.x), "=f"(f.y) : "l"(v)); return f;
}
__device__ __forceinline__ void ffma2(ull& d, ull a, ull b) {
    asm("fma.rn.f32x2 %0, %1, %2, %0;" : "+l"(d) : "l"(a), "l"(b));
}
__device__ __forceinline__ ull add2(ull a, ull b) {
    ull r; asm("add.rn.f32x2 %0, %1, %2;" : "=l"(r) : "l"(a), "l"(b)); return r;
}
__device__ __forceinline__ void lds2u64(ull& a, ull& b, uint32_t addr) {
    asm volatile("ld.shared.v2.u64 {%0,%1}, [%2];" : "=l"(a), "=l"(b) : "r"(addr));
}
__device__ __forceinline__ float sigf(float x) {
    return __fdividef(1.0f, 1.0f + __expf(-x));
}
__device__ __forceinline__ float tanh_ex(float x) {
    return fmaf(2.0f, sigf(2.0f * x), -1.0f);
}
__device__ __forceinline__ float nanfix(float v) { return (v == v) ? v : 1.0f; }

__device__ __forceinline__ void cpasync16(uint32_t dst, const void* src) {
    asm volatile("cp.async.cg.shared.global [%0], [%1], 16;" :: "r"(dst), "l"(src));
}
#define CP_COMMIT() asm volatile("cp.async.commit_group;")
#define CP_WAIT0()  asm volatile("cp.async.wait_group 0;")

__global__ void __launch_bounds__(THREADS, 4)
rnncf_kernel(const float* __restrict__ inp,        // (NV, NT, 12)
             const float* __restrict__ init_state, // (NV, 2)
             const float* __restrict__ h0,         // (NV, 20)
             const float* __restrict__ c0,         // (NV, 20)
             const float* __restrict__ Wk,         // (12, 80)
             const float* __restrict__ Wr,         // (20, 80)
             const float* __restrict__ bz,         // (80)
             const float* __restrict__ d2w,        // (20, 10)
             const float* __restrict__ d2b,        // (10)
             const float* __restrict__ lcw,        // (10, 3)
             const float* __restrict__ lcb,        // (3)
             const float* __restrict__ d1w,        // (10, 1)
             const float* __restrict__ d1b,        // (1)
             float* __restrict__ out)
{
    // xdup[buf][v][k]: k=0..11 -> (cur_k,cur_k) dup; k=12..31 -> (h,h) dup
    __shared__ ull  xdup[2][VB][32];
    __shared__ __align__(16) float raws[2][VB][12];
    __shared__ float xs[VB][12];
    __shared__ float s_spd[VB];
    __shared__ float s_d2t[10][UNITS];    // d2w transposed [col][k]
    __shared__ float s_d2b[10];
    __shared__ float s_head[10][4];       // [m][q]: q<3 -> lcw col q, q=3 -> d1w
    __shared__ float s_headb[4];

    const int tid  = threadIdx.x;
    const int grpv = tid / 40;          // vehicle-pair group 0..3
    const int r    = tid % 40;
    const int u    = r >> 1;            // unit 0..19
    const int p    = r & 1;             // 0 -> (i,f), 1 -> (g,o)
    const int v0   = grpv * 2;
    const int vbase0 = blockIdx.x * VB;

    // ---- static head weights -> smem ----
    for (int i = tid; i < 200; i += THREADS) s_d2t[i % 10][i / 10] = d2w[i];
    if (tid < 10) s_d2b[tid] = d2b[tid];
    if (tid < 40) { int m = tid >> 2, q = tid & 3; s_head[m][q] = (q < 3) ? lcw[m * 3 + q] : d1w[m]; }
    if (tid < 4)  s_headb[tid] = (tid < 3) ? lcb[tid] : d1b[0];

    // ---- branchless activation constants ----
    const float kA = p ? 2.0f : 1.0f;   // act_a = fmaf(mA, sigf(kA*z), cA)
    const float mA = p ? 2.0f : 1.0f;   // p=0: sigmoid; p=1: tanh
    const float cA = p ? -1.0f : 0.0f;

    // ---- register-resident gate-pair weight column ----
    const int colA = p ? (40 + u) : u;
    const int colB = p ? (60 + u) : (20 + u);
    ull w2[32];
#pragma unroll
    for (int k = 0; k < 32; k++) {
        float wa = (k < IND) ? Wk[k * NCOL + colA] : Wr[(k - IND) * NCOL + colA];
        float wb = (k < IND) ? Wk[k * NCOL + colB] : Wr[(k - IND) * NCOL + colB];
        w2[k] = pk(wa, wb);
    }
    const ull bias2 = pk(bz[colA], bz[colB]);
    const ull zero2 = pk(0.0f, 0.0f);

    // ---- state init ----
    float c2[2];
    c2[0] = c0[(vbase0 + v0 + 0) * UNITS + u];
    c2[1] = c0[(vbase0 + v0 + 1) * UNITS + u];
    float pos = 0.0f;

    {   // h0 dup into xdup[0] (160 threads cover 8*20)
        int v = tid / UNITS, uu = tid % UNITS;
        float h = h0[(vbase0 + v) * UNITS + uu];
        xdup[0][v][12 + uu] = pk(h, h);
    }
    if (tid >= 80 && tid < 80 + VB) {
        const int ov = tid - 80;
        const int vg = vbase0 + ov;
        pos = init_state[vg * 2 + 0];
        s_spd[ov] = init_state[vg * 2 + 1];
        const float4* ip = (const float4*)(inp + (size_t)vg * NT * 12);
        float4 r0 = ip[0], r1 = ip[1], r2 = ip[2];
        ull* cb = &xdup[0][ov][0];
        const float ih = 0.01f, iv = 0.025f;
        float t0;
        t0 = nanfix((r0.x - pos) * ih); cb[0]  = pk(t0, t0);
        t0 = nanfix((r0.y - pos) * ih); cb[1]  = pk(t0, t0);
        t0 = nanfix((r0.z - pos) * ih); cb[2]  = pk(t0, t0);
        t0 = nanfix((pos - r0.w) * ih); cb[3]  = pk(t0, t0);
        t0 = nanfix((pos - r1.x) * ih); cb[4]  = pk(t0, t0);
        t0 = nanfix((pos - r1.y) * ih); cb[5]  = pk(t0, t0);
        t0 = nanfix(r1.z * iv);         cb[6]  = pk(t0, t0);
        t0 = nanfix(r1.w * iv);         cb[7]  = pk(t0, t0);
        t0 = nanfix(r2.x * iv);         cb[8]  = pk(t0, t0);
        t0 = nanfix(r2.y * iv);         cb[9]  = pk(t0, t0);
        t0 = nanfix(r2.z * iv);         cb[10] = pk(t0, t0);
        t0 = nanfix(r2.w * iv);         cb[11] = pk(t0, t0);
        uint32_t d = (uint32_t)__cvta_generic_to_shared(&raws[1][ov][0]);
        const float* src = inp + ((size_t)vg * NT + 1) * 12;
        cpasync16(d, src); cpasync16(d + 16, src + 4); cpasync16(d + 32, src + 8);
        CP_COMMIT();
    }
    __syncthreads();

    for (int t = 0; t < NT; t++) {
        const int tb = t & 1;

        // ---- Phase A: LSTM matvec + gates + cell (all 160 threads) ----
#pragma unroll
        for (int vi = 0; vi < 2; vi++) {
            const int v = v0 + vi;
            uint32_t xb = (uint32_t)__cvta_generic_to_shared(&xdup[tb][v][0]);
            ull a0 = bias2, a1 = zero2;
#pragma unroll
            for (int q = 0; q < 16; q++) {
                ull xa, xc;
                lds2u64(xa, xc, xb + q * 16);
                ffma2(a0, xa, w2[2 * q]);
                ffma2(a1, xc, w2[2 * q + 1]);
            }
            float2 z = unpk(add2(a0, a1));
            float act_a = fmaf(mA, sigf(kA * z.x), cA);   // p0: sig(z_i); p1: tanh(z_g)
            float act_b = sigf(z.y);                      // p0: sig(z_f); p1: sig(z_o)
            float oa = __shfl_xor_sync(0xFFFFFFFFu, act_a, 1);
            float ob = __shfl_xor_sync(0xFFFFFFFFu, act_b, 1);
            float si = p ? oa : act_a;
            float sf = p ? ob : act_b;
            float tg = p ? act_a : oa;
            float so = p ? act_b : ob;
            float cc = fmaf(sf, c2[vi], si * tg);
            c2[vi] = cc;
            float h = so * tanh_ex(cc);
            if (p == 0) xdup[tb ^ 1][v][12 + u] = pk(h, h);
        }
        __syncthreads();   // barrier 1: h(t) visible

        // ---- Phase B: head-x (80 thr) + cur(t+1)/pos (8 thr) ----
        if (tid < 80) {
            const int xv = tid / 10, xc = tid % 10;
            const float* hb = (const float*)&xdup[tb ^ 1][xv][12];  // h_k at hb[2k]
            const float4* wr = (const float4*)&s_d2t[xc][0];
            float acc = s_d2b[xc];
#pragma unroll
            for (int m = 0; m < 5; m++) {
                float4 W = wr[m];
                acc = fmaf(hb[(4 * m + 0) * 2], W.x, acc);
                acc = fmaf(hb[(4 * m + 1) * 2], W.y, acc);
                acc = fmaf(hb[(4 * m + 2) * 2], W.z, acc);
                acc = fmaf(hb[(4 * m + 3) * 2], W.w, acc);
            }
            xs[xv][xc] = fmaxf(acc, 0.0f);
        } else if (tid < 80 + VB) {
            const int ov = tid - 80;
            const int vg = vbase0 + ov;
            CP_WAIT0();                        // raw(t+1) landed
            float spd = s_spd[ov];
            pos = fmaf(0.1f, spd, pos);        // pos(t+1) = reference pos output at t
            out[OUT_POS + (size_t)vg * NT + t] = pos;
            const float4* rw = (const float4*)&raws[(t + 1) & 1][ov][0];
            float4 r0 = rw[0], r1 = rw[1], r2 = rw[2];
            ull* cb = &xdup[tb ^ 1][ov][0];
            const float ih = 0.01f, iv = 0.025f;
            float t0;
            t0 = nanfix((r0.x - pos) * ih); cb[0]  = pk(t0, t0);
            t0 = nanfix((r0.y - pos) * ih); cb[1]  = pk(t0, t0);
            t0 = nanfix((r0.z - pos) * ih); cb[2]  = pk(t0, t0);
            t0 = nanfix((pos - r0.w) * ih); cb[3]  = pk(t0, t0);
            t0 = nanfix((pos - r1.x) * ih); cb[4]  = pk(t0, t0);
            t0 = nanfix((pos - r1.y) * ih); cb[5]  = pk(t0, t0);
            t0 = nanfix(r1.z * iv);         cb[6]  = pk(t0, t0);
            t0 = nanfix(r1.w * iv);         cb[7]  = pk(t0, t0);
            t0 = nanfix(r2.x * iv);         cb[8]  = pk(t0, t0);
            t0 = nanfix(r2.y * iv);         cb[9]  = pk(t0, t0);
            t0 = nanfix(r2.z * iv);         cb[10] = pk(t0, t0);
            t0 = nanfix(r2.w * iv);         cb[11] = pk(t0, t0);
            if (t + 2 < NT) {                  // prefetch raw(t+2)
                uint32_t d = (uint32_t)__cvta_generic_to_shared(&raws[t & 1][ov][0]);
                const float* src = inp + ((size_t)vg * NT + (t + 2)) * 12;
                cpasync16(d, src); cpasync16(d + 16, src + 4); cpasync16(d + 32, src + 8);
                CP_COMMIT();
            }
        }
        __syncthreads();   // barrier 2: xs + cur(t+1) + h visible

        // ---- Phase C: lc / acc / spd update (32 threads; no trailing barrier) ----
        if (tid < 4 * VB) {
            const int cv = tid >> 2, cq = tid & 3;
            const int vg = vbase0 + cv;
            float acc = s_headb[cq];
#pragma unroll
            for (int m = 0; m < 10; m++) acc = fmaf(xs[cv][m], s_head[m][cq], acc);
            if (cq < 3) {
                out[OUT_LC + ((size_t)vg * NT + t) * 3 + cq] = acc;
            } else {
                float a = fmaf(10.0f, acc, -6.0f);
                s_spd[cv] = fmaf(0.1f, a, s_spd[cv]);
            }
        }
        // C(t) reads xs / writes s_spd; B(t+1) writes xs / reads s_spd — ordered
        // by barrier 1 of step t+1. A(t+1) touches only xdup buffers, disjoint.
    }

    __syncthreads();
    // ---- finals ----
    if (tid < VB) out[OUT_SPD + vbase0 + tid] = s_spd[tid];
    {
        int v = tid / UNITS, uu = tid % UNITS;   // 160 threads cover VB*20
        out[OUT_H + (size_t)(vbase0 + v) * UNITS + uu] =
            ((const float*)&xdup[NT & 1][v][12 + uu])[0];
    }
    if (p == 0) {
        out[OUT_C + (size_t)(vbase0 + v0 + 0) * UNITS + u] = c2[0];
        out[OUT_C + (size_t)(vbase0 + v0 + 1) * UNITS + u] = c2[1];
    }
}

extern "C" void kernel_launch(void* const* d_in, const int* in_sizes, int n_in,
                              void* d_out, int out_size) {
    const float* inp        = (const float*)d_in[0];
    const float* init_state = (const float*)d_in[1];
    const float* h0         = (const float*)d_in[2];
    const float* c0         = (const float*)d_in[3];
    const float* Wk         = (const float*)d_in[4];
    const float* Wr         = (const float*)d_in[5];
    const float* bzv        = (const float*)d_in[6];
    const float* d2w        = (const float*)d_in[7];
    const float* d2b        = (const float*)d_in[8];
    const float* lcw        = (const float*)d_in[9];
    const float* lcb        = (const float*)d_in[10];
    const float* d1w        = (const float*)d_in[11];
    const float* d1b        = (const float*)d_in[12];
    float* out = (float*)d_out;

    rnncf_kernel<<<BLOCKS, THREADS>>>(inp, init_state, h0, c0, Wk, Wr, bzv,
                                      d2w, d2b, lcw, lcb, d1w, d1b, out);
}

// round 5
// speedup vs baseline: 1.5367x; 1.4595x over previous
#include <cuda_runtime.h>
#include <cstdint>

#define NV     8192
#define NT     1000
#define UNITS  20
#define IND    12
#define NCOL   80
#define VB     8            // vehicles per block
#define THREADS 160         // 4 groups of 40 threads; group serves 2 vehicles
#define BLOCKS (NV/VB)      // 1024

// output packing (flat concat in reference return order)
#define OUT_POS 0
#define OUT_LC  (NV*NT)
#define OUT_SPD (OUT_LC + NV*NT*3)
#define OUT_H   (OUT_SPD + NV)
#define OUT_C   (OUT_H + NV*UNITS)

typedef unsigned long long ull;

__device__ __forceinline__ ull pk(float x, float y) {
    ull r; asm("mov.b64 %0, {%1,%2};" : "=l"(r) : "f"(x), "f"(y)); return r;
}
__device__ __forceinline__ float2 unpk(ull v) {
    float2 f; asm("mov.b64 {%0,%1}, %2;" : "=f"(f.x), "=f"(f.y) : "l"(v)); return f;
}
__device__ __forceinline__ void ffma2(ull& d, ull a, ull b) {
    asm("fma.rn.f32x2 %0, %1, %2, %0;" : "+l"(d) : "l"(a), "l"(b));
}
__device__ __forceinline__ ull add2(ull a, ull b) {
    ull r; asm("add.rn.f32x2 %0, %1, %2;" : "=l"(r) : "l"(a), "l"(b)); return r;
}
__device__ __forceinline__ void lds2u64(ull& a, ull& b, uint32_t addr) {
    asm volatile("ld.shared.v2.u64 {%0,%1}, [%2];" : "=l"(a), "=l"(b) : "r"(addr));
}
__device__ __forceinline__ float sigf(float x) {
    return __fdividef(1.0f, 1.0f + __expf(-x));
}
__device__ __forceinline__ float tanh_ex(float x) {
    return fmaf(2.0f, sigf(2.0f * x), -1.0f);
}
__device__ __forceinline__ float nanfix(float v) { return (v == v) ? v : 1.0f; }

__device__ __forceinline__ void cpasync16(uint32_t dst, const void* src) {
    asm volatile("cp.async.cg.shared.global [%0], [%1], 16;" :: "r"(dst), "l"(src));
}
#define CP_COMMIT() asm volatile("cp.async.commit_group;")
#define CP_WAIT0()  asm volatile("cp.async.wait_group 0;")

__global__ void __launch_bounds__(THREADS, 4)
rnncf_kernel(const float* __restrict__ inp,        // (NV, NT, 12)
             const float* __restrict__ init_state, // (NV, 2)
             const float* __restrict__ h0,         // (NV, 20)
             const float* __restrict__ c0,         // (NV, 20)
             const float* __restrict__ Wk,         // (12, 80)
             const float* __restrict__ Wr,         // (20, 80)
             const float* __restrict__ bz,         // (80)
             const float* __restrict__ d2w,        // (20, 10)
             const float* __restrict__ d2b,        // (10)
             const float* __restrict__ lcw,        // (10, 3)
             const float* __restrict__ lcb,        // (3)
             const float* __restrict__ d1w,        // (10, 1)
             const float* __restrict__ d1b,        // (1)
             float* __restrict__ out)
{
    // xin[buf][v]: floats 0..11 = cur, 12..31 = h  (stored once, no duplication)
    __shared__ __align__(16) float xin[2][VB][32];
    __shared__ __align__(16) float raws[2][VB][12];
    __shared__ float xs[VB][12];
    __shared__ float s_spd[VB];
    __shared__ __align__(16) float s_d2t[10][UNITS];  // d2w transposed [col][k]
    __shared__ float s_d2b[10];
    __shared__ float s_head[10][4];       // [m][q]: q<3 -> lcw col q, q=3 -> d1w
    __shared__ float s_headb[4];

    const int tid  = threadIdx.x;
    const int grpv = tid / 40;          // vehicle-pair group 0..3
    const int r    = tid % 40;
    const int u    = r >> 1;            // unit 0..19
    const int p    = r & 1;             // 0 -> (i,f) columns, 1 -> (g,o) columns
    const int v0   = grpv * 2;
    const int vbase0 = blockIdx.x * VB;

    // ---- static head weights -> smem ----
    for (int i = tid; i < 200; i += THREADS) s_d2t[i % 10][i / 10] = d2w[i];
    if (tid < 10) s_d2b[tid] = d2b[tid];
    if (tid < 40) { int m = tid >> 2, q = tid & 3; s_head[m][q] = (q < 3) ? lcw[m * 3 + q] : d1w[m]; }
    if (tid < 4)  s_headb[tid] = (tid < 3) ? lcb[tid] : d1b[0];

    // ---- branchless activation constants (for column A) ----
    const float kA = p ? 2.0f : 1.0f;   // actA = fmaf(mA, sigf(kA*z), cA)
    const float mA = p ? 2.0f : 1.0f;   // p=0: sigmoid(z_i); p=1: tanh(z_g)
    const float cA = p ? -1.0f : 0.0f;

    // ---- register-resident weights: two columns, packed across k ----
    const int colA = p ? (40 + u) : u;          // g or i
    const int colB = p ? (60 + u) : (20 + u);   // o or f
    ull wA[16], wB[16];
#pragma unroll
    for (int q = 0; q < 16; q++) {
        int k0 = 2 * q, k1 = 2 * q + 1;
        float a0 = (k0 < IND) ? Wk[k0 * NCOL + colA] : Wr[(k0 - IND) * NCOL + colA];
        float a1 = (k1 < IND) ? Wk[k1 * NCOL + colA] : Wr[(k1 - IND) * NCOL + colA];
        wA[q] = pk(a0, a1);
        float b0 = (k0 < IND) ? Wk[k0 * NCOL + colB] : Wr[(k0 - IND) * NCOL + colB];
        float b1 = (k1 < IND) ? Wk[k1 * NCOL + colB] : Wr[(k1 - IND) * NCOL + colB];
        wB[q] = pk(b0, b1);
    }
    const float bzA = bz[colA], bzB = bz[colB];
    const ull zero2 = pk(0.0f, 0.0f);

    // ---- state init ----
    float c2[2];
    c2[0] = c0[(vbase0 + v0 + 0) * UNITS + u];
    c2[1] = c0[(vbase0 + v0 + 1) * UNITS + u];
    float pos = 0.0f;

    {   // h0 -> xin[0] (160 threads cover 8*20)
        int v = tid / UNITS, uu = tid % UNITS;
        xin[0][v][12 + uu] = h0[(vbase0 + v) * UNITS + uu];
    }
    if (tid >= 80 && tid < 80 + VB) {
        const int ov = tid - 80;
        const int vg = vbase0 + ov;
        pos = init_state[vg * 2 + 0];
        s_spd[ov] = init_state[vg * 2 + 1];
        const float4* ip = (const float4*)(inp + (size_t)vg * NT * 12);
        float4 r0 = ip[0], r1 = ip[1], r2 = ip[2];
        float* cb = &xin[0][ov][0];
        const float ih = 0.01f, iv = 0.025f;
        cb[0]  = nanfix((r0.x - pos) * ih);
        cb[1]  = nanfix((r0.y - pos) * ih);
        cb[2]  = nanfix((r0.z - pos) * ih);
        cb[3]  = nanfix((pos - r0.w) * ih);
        cb[4]  = nanfix((pos - r1.x) * ih);
        cb[5]  = nanfix((pos - r1.y) * ih);
        cb[6]  = nanfix(r1.z * iv);
        cb[7]  = nanfix(r1.w * iv);
        cb[8]  = nanfix(r2.x * iv);
        cb[9]  = nanfix(r2.y * iv);
        cb[10] = nanfix(r2.z * iv);
        cb[11] = nanfix(r2.w * iv);
        uint32_t d = (uint32_t)__cvta_generic_to_shared(&raws[1][ov][0]);
        const float* src = inp + ((size_t)vg * NT + 1) * 12;
        cpasync16(d, src); cpasync16(d + 16, src + 4); cpasync16(d + 32, src + 8);
        CP_COMMIT();
    }
    __syncthreads();

    for (int t = 0; t < NT; t++) {
        const int tb = t & 1;

        // ---- Phase A: LSTM matvec + gates + cell (all 160 threads) ----
#pragma unroll
        for (int vi = 0; vi < 2; vi++) {
            const int v = v0 + vi;
            uint32_t xb = (uint32_t)__cvta_generic_to_shared(&xin[tb][v][0]);
            ull aA0 = pk(bzA, 0.0f), aA1 = zero2;
            ull aB0 = pk(bzB, 0.0f), aB1 = zero2;
#pragma unroll
            for (int q = 0; q < 8; q++) {       // 16B of x feeds 4 FFMA2
                ull xa, xc;
                lds2u64(xa, xc, xb + q * 16);
                ffma2(aA0, xa, wA[2 * q]);
                ffma2(aB0, xa, wB[2 * q]);
                ffma2(aA1, xc, wA[2 * q + 1]);
                ffma2(aB1, xc, wB[2 * q + 1]);
            }
            float2 fA = unpk(add2(aA0, aA1));
            float2 fB = unpk(add2(aB0, aB1));
            float zA = fA.x + fA.y;
            float zB = fB.x + fB.y;
            float actA = fmaf(mA, sigf(kA * zA), cA);  // p0: sig(i); p1: tanh(g)
            float actB = sigf(zB);                     // p0: sig(f); p1: sig(o)
            float oa = __shfl_xor_sync(0xFFFFFFFFu, actA, 1);  // partner's A
            float ob = __shfl_xor_sync(0xFFFFFFFFu, actB, 1);  // partner's B
            if (p == 0) {   // p0 now holds: si=actA, sf=actB, tg=oa, so=ob
                float cc = fmaf(actB, c2[vi], actA * oa);
                c2[vi] = cc;
                xin[tb ^ 1][v][12 + u] = ob * tanh_ex(cc);
            }
        }
        __syncthreads();   // barrier 1: h(t) visible

        // ---- Phase B: head-x (80 thr) + cur(t+1)/pos (8 thr) ----
        if (tid < 80) {
            const int xv = tid / 10, xc = tid % 10;
            const float4* hr = (const float4*)(&xin[tb ^ 1][xv][12]);
            const float4* wr = (const float4*)&s_d2t[xc][0];
            float acc = s_d2b[xc], ac1 = 0.0f;
#pragma unroll
            for (int m = 0; m < 5; m++) {
                float4 H = hr[m], W = wr[m];
                acc = fmaf(H.x, W.x, acc);
                ac1 = fmaf(H.y, W.y, ac1);
                acc = fmaf(H.z, W.z, acc);
                ac1 = fmaf(H.w, W.w, ac1);
            }
            xs[xv][xc] = fmaxf(acc + ac1, 0.0f);
        } else if (tid < 80 + VB) {
            const int ov = tid - 80;
            const int vg = vbase0 + ov;
            CP_WAIT0();                        // raw(t+1) landed
            float spd = s_spd[ov];
            pos = fmaf(0.1f, spd, pos);        // pos(t+1) = reference pos output at t
            out[OUT_POS + (size_t)vg * NT + t] = pos;
            const float4* rw = (const float4*)&raws[(t + 1) & 1][ov][0];
            float4 r0 = rw[0], r1 = rw[1], r2 = rw[2];
            float* cb = &xin[tb ^ 1][ov][0];
            const float ih = 0.01f, iv = 0.025f;
            cb[0]  = nanfix((r0.x - pos) * ih);
            cb[1]  = nanfix((r0.y - pos) * ih);
            cb[2]  = nanfix((r0.z - pos) * ih);
            cb[3]  = nanfix((pos - r0.w) * ih);
            cb[4]  = nanfix((pos - r1.x) * ih);
            cb[5]  = nanfix((pos - r1.y) * ih);
            cb[6]  = nanfix(r1.z * iv);
            cb[7]  = nanfix(r1.w * iv);
            cb[8]  = nanfix(r2.x * iv);
            cb[9]  = nanfix(r2.y * iv);
            cb[10] = nanfix(r2.z * iv);
            cb[11] = nanfix(r2.w * iv);
            if (t + 2 < NT) {                  // prefetch raw(t+2)
                uint32_t d = (uint32_t)__cvta_generic_to_shared(&raws[t & 1][ov][0]);
                const float* src = inp + ((size_t)vg * NT + (t + 2)) * 12;
                cpasync16(d, src); cpasync16(d + 16, src + 4); cpasync16(d + 32, src + 8);
                CP_COMMIT();
            }
        }
        __syncthreads();   // barrier 2: xs + cur(t+1) + h visible

        // ---- Phase C: lc / acc / spd update (32 threads; no trailing barrier) ----
        if (tid < 4 * VB) {
            const int cv = tid >> 2, cq = tid & 3;
            const int vg = vbase0 + cv;
            float acc = s_headb[cq];
#pragma unroll
            for (int m = 0; m < 10; m++) acc = fmaf(xs[cv][m], s_head[m][cq], acc);
            if (cq < 3) {
                out[OUT_LC + ((size_t)vg * NT + t) * 3 + cq] = acc;
            } else {
                float a = fmaf(10.0f, acc, -6.0f);
                s_spd[cv] = fmaf(0.1f, a, s_spd[cv]);
            }
        }
        // C(t) reads xs / writes s_spd; B(t+1) writes xs / reads s_spd — ordered
        // by barrier 1 of step t+1. A(t+1) touches only xin buffers, disjoint.
    }

    __syncthreads();
    // ---- finals ----
    if (tid < VB) out[OUT_SPD + vbase0 + tid] = s_spd[tid];
    {
        int v = tid / UNITS, uu = tid % UNITS;   // 160 threads cover VB*20
        out[OUT_H + (size_t)(vbase0 + v) * UNITS + uu] = xin[NT & 1][v][12 + uu];
    }
    if (p == 0) {
        out[OUT_C + (size_t)(vbase0 + v0 + 0) * UNITS + u] = c2[0];
        out[OUT_C + (size_t)(vbase0 + v0 + 1) * UNITS + u] = c2[1];
    }
}

extern "C" void kernel_launch(void* const* d_in, const int* in_sizes, int n_in,
                              void* d_out, int out_size) {
    const float* inp        = (const float*)d_in[0];
    const float* init_state = (const float*)d_in[1];
    const float* h0         = (const float*)d_in[2];
    const float* c0         = (const float*)d_in[3];
    const float* Wk         = (const float*)d_in[4];
    const float* Wr         = (const float*)d_in[5];
    const float* bzv        = (const float*)d_in[6];
    const float* d2w        = (const float*)d_in[7];
    const float* d2b        = (const float*)d_in[8];
    const float* lcw        = (const float*)d_in[9];
    const float* lcb        = (const float*)d_in[10];
    const float* d1w        = (const float*)d_in[11];
    const float* d1b        = (const float*)d_in[12];
    float* out = (float*)d_out;

    rnncf_kernel<<<BLOCKS, THREADS>>>(inp, init_state, h0, c0, Wk, Wr, bzv,
                                      d2w, d2b, lcw, lcb, d1w, d1b, out);
}

// round 7
// speedup vs baseline: 1.6206x; 1.0546x over previous
#include <cuda_runtime.h>
#include <cstdint>

#define NV     8192
#define NT     1000
#define UNITS  20
#define IND    12
#define NCOL   80
#define VB     16           // vehicles per block
#define THREADS 160         // 4 groups of 40 threads; group serves 4 vehicles
#define BLOCKS (NV/VB)      // 512  -> one residency wave (<=592 slots)

// output packing (flat concat in reference return order)
#define OUT_POS 0
#define OUT_LC  (NV*NT)
#define OUT_SPD (OUT_LC + NV*NT*3)
#define OUT_H   (OUT_SPD + NV)
#define OUT_C   (OUT_H + NV*UNITS)

typedef unsigned long long ull;

__device__ __forceinline__ ull pk(float x, float y) {
    ull r; asm("mov.b64 %0, {%1,%2};" : "=l"(r) : "f"(x), "f"(y)); return r;
}
__device__ __forceinline__ float2 unpk(ull v) {
    float2 f; asm("mov.b64 {%0,%1}, %2;" : "=f"(f.x), "=f"(f.y) : "l"(v)); return f;
}
__device__ __forceinline__ void ffma2(ull& d, ull a, ull b) {
    asm("fma.rn.f32x2 %0, %1, %2, %0;" : "+l"(d) : "l"(a), "l"(b));
}
__device__ __forceinline__ ull add2(ull a, ull b) {
    ull r; asm("add.rn.f32x2 %0, %1, %2;" : "=l"(r) : "l"(a), "l"(b)); return r;
}
__device__ __forceinline__ void lds2u64(ull& a, ull& b, uint32_t addr) {
    asm volatile("ld.shared.v2.u64 {%0,%1}, [%2];" : "=l"(a), "=l"(b) : "r"(addr));
}
__device__ __forceinline__ float sigf(float x) {
    return __fdividef(1.0f, 1.0f + __expf(-x));
}
__device__ __forceinline__ float tanh_ex(float x) {
    return fmaf(2.0f, sigf(2.0f * x), -1.0f);
}
__device__ __forceinline__ float nanfix(float v) { return (v == v) ? v : 1.0f; }

__device__ __forceinline__ void cpasync16(uint32_t dst, const void* src) {
    asm volatile("cp.async.cg.shared.global [%0], [%1], 16;" :: "r"(dst), "l"(src));
}
#define CP_COMMIT() asm volatile("cp.async.commit_group;")
#define CP_WAIT0()  asm volatile("cp.async.wait_group 0;")

__global__ void __launch_bounds__(THREADS, 4)
rnncf_kernel(const float* __restrict__ inp,        // (NV, NT, 12)
             const float* __restrict__ init_state, // (NV, 2)
             const float* __restrict__ h0,         // (NV, 20)
             const float* __restrict__ c0,         // (NV, 20)
             const float* __restrict__ Wk,         // (12, 80)
             const float* __restrict__ Wr,         // (20, 80)
             const float* __restrict__ bz,         // (80)
             const float* __restrict__ d2w,        // (20, 10)
             const float* __restrict__ d2b,        // (10)
             const float* __restrict__ lcw,        // (10, 3)
             const float* __restrict__ lcb,        // (3)
             const float* __restrict__ d1w,        // (10, 1)
             const float* __restrict__ d1b,        // (1)
             float* __restrict__ out)
{
    // xin[buf][v]: floats 0..11 = cur, 12..31 = h  (stored once)
    __shared__ __align__(16) float xin[2][VB][32];
    __shared__ __align__(16) float raws[2][VB][12];
    __shared__ float xs[VB][12];
    __shared__ float s_spd[VB];
    __shared__ __align__(16) float s_d2t[10][UNITS];  // d2w transposed [col][k]
    __shared__ float s_d2b[10];
    __shared__ float s_head[10][4];       // [m][q]: q<3 -> lcw col q, q=3 -> d1w
    __shared__ float s_headb[4];

    const int tid  = threadIdx.x;
    const int grpv = tid / 40;          // group 0..3, serves 4 vehicles
    const int r    = tid % 40;
    const int u    = r >> 1;            // unit 0..19
    const int p    = r & 1;             // 0 -> (i,f) columns, 1 -> (g,o) columns
    const int v0   = grpv * 4;
    const int vbase0 = blockIdx.x * VB;

    // ---- static head weights -> smem ----
    for (int i = tid; i < 200; i += THREADS) s_d2t[i % 10][i / 10] = d2w[i];
    if (tid < 10) s_d2b[tid] = d2b[tid];
    if (tid < 40) { int m = tid >> 2, q = tid & 3; s_head[m][q] = (q < 3) ? lcw[m * 3 + q] : d1w[m]; }
    if (tid < 4)  s_headb[tid] = (tid < 3) ? lcb[tid] : d1b[0];

    // ---- branchless activation constants (for column A) ----
    const float kA = p ? 2.0f : 1.0f;   // actA = fmaf(mA, sigf(kA*z), cA)
    const float mA = p ? 2.0f : 1.0f;   // p=0: sigmoid(z_i); p=1: tanh(z_g)
    const float cA = p ? -1.0f : 0.0f;

    // ---- register-resident weights: two columns, packed across k ----
    const int colA = p ? (40 + u) : u;          // g or i
    const int colB = p ? (60 + u) : (20 + u);   // o or f
    ull wA[16], wB[16];
#pragma unroll
    for (int q = 0; q < 16; q++) {
        int k0 = 2 * q, k1 = 2 * q + 1;
        float a0 = (k0 < IND) ? Wk[k0 * NCOL + colA] : Wr[(k0 - IND) * NCOL + colA];
        float a1 = (k1 < IND) ? Wk[k1 * NCOL + colA] : Wr[(k1 - IND) * NCOL + colA];
        wA[q] = pk(a0, a1);
        float b0 = (k0 < IND) ? Wk[k0 * NCOL + colB] : Wr[(k0 - IND) * NCOL + colB];
        float b1 = (k1 < IND) ? Wk[k1 * NCOL + colB] : Wr[(k1 - IND) * NCOL + colB];
        wB[q] = pk(b0, b1);
    }
    const float bzA = bz[colA], bzB = bz[colB];
    const ull zero2 = pk(0.0f, 0.0f);

    // ---- state init ----
    float c2[4];
#pragma unroll
    for (int vi = 0; vi < 4; vi++)
        c2[vi] = c0[(vbase0 + v0 + vi) * UNITS + u];
    float pos = 0.0f;

    for (int i = tid; i < VB * UNITS; i += THREADS) {   // h0 -> xin[0]
        int v = i / UNITS, uu = i % UNITS;
        xin[0][v][12 + uu] = h0[(vbase0 + v) * UNITS + uu];
    }
    if (tid < VB) {                     // vehicle owners: tid = vehicle index
        const int ov = tid;
        const int vg = vbase0 + ov;
        pos = init_state[vg * 2 + 0];
        s_spd[ov] = init_state[vg * 2 + 1];
        const float4* ip = (const float4*)(inp + (size_t)vg * NT * 12);
        float4 r0 = ip[0], r1 = ip[1], r2 = ip[2];
        float* cb = &xin[0][ov][0];
        const float ih = 0.01f, iv = 0.025f;
        cb[0]  = nanfix((r0.x - pos) * ih);
        cb[1]  = nanfix((r0.y - pos) * ih);
        cb[2]  = nanfix((r0.z - pos) * ih);
        cb[3]  = nanfix((pos - r0.w) * ih);
        cb[4]  = nanfix((pos - r1.x) * ih);
        cb[5]  = nanfix((pos - r1.y) * ih);
        cb[6]  = nanfix(r1.z * iv);
        cb[7]  = nanfix(r1.w * iv);
        cb[8]  = nanfix(r2.x * iv);
        cb[9]  = nanfix(r2.y * iv);
        cb[10] = nanfix(r2.z * iv);
        cb[11] = nanfix(r2.w * iv);
        uint32_t d = (uint32_t)__cvta_generic_to_shared(&raws[1][ov][0]);
        const float* src = inp + ((size_t)vg * NT + 1) * 12;
        cpasync16(d, src); cpasync16(d + 16, src + 4); cpasync16(d + 32, src + 8);
        CP_COMMIT();
    }
    __syncthreads();

    for (int t = 0; t < NT; t++) {
        const int tb = t & 1;

        // ---- Phase A: LSTM matvec + gates + cell, 4 vehicles (all 160 thr) ----
#pragma unroll
        for (int vi = 0; vi < 4; vi++) {
            const int v = v0 + vi;
            uint32_t xb = (uint32_t)__cvta_generic_to_shared(&xin[tb][v][0]);
            ull aA0 = pk(bzA, 0.0f), aA1 = zero2;
            ull aB0 = pk(bzB, 0.0f), aB1 = zero2;
#pragma unroll
            for (int q = 0; q < 8; q++) {       // 16B of x feeds 4 FFMA2
                ull xa, xc;
                lds2u64(xa, xc, xb + q * 16);
                ffma2(aA0, xa, wA[2 * q]);
                ffma2(aB0, xa, wB[2 * q]);
                ffma2(aA1, xc, wA[2 * q + 1]);
                ffma2(aB1, xc, wB[2 * q + 1]);
            }
            float2 fA = unpk(add2(aA0, aA1));
            float2 fB = unpk(add2(aB0, aB1));
            float zA = fA.x + fA.y;
            float zB = fB.x + fB.y;
            float actA = fmaf(mA, sigf(kA * zA), cA);  // p0: sig(i); p1: tanh(g)
            float actB = sigf(zB);                     // p0: sig(f); p1: sig(o)
            float oa = __shfl_xor_sync(0xFFFFFFFFu, actA, 1);  // partner's A
            float ob = __shfl_xor_sync(0xFFFFFFFFu, actB, 1);  // partner's B
            if (p == 0) {   // p0 holds: si=actA, sf=actB, tg=oa, so=ob
                float cc = fmaf(actB, c2[vi], actA * oa);
                c2[vi] = cc;
                xin[tb ^ 1][v][12 + u] = ob * tanh_ex(cc);
            }
        }
        __syncthreads();   // barrier 1: h(t) visible

        // ---- Phase B: head-x (all 160 thr) + owner work (16 thr tail) ----
        {
            const int xv = tid / 10, xc = tid % 10;       // 16 veh x 10 cols = 160
            const float4* hr = (const float4*)(&xin[tb ^ 1][xv][12]);
            const float4* wr = (const float4*)&s_d2t[xc][0];
            float acc = s_d2b[xc], ac1 = 0.0f;
#pragma unroll
            for (int m = 0; m < 5; m++) {
                float4 H = hr[m], W = wr[m];
                acc = fmaf(H.x, W.x, acc);
                ac1 = fmaf(H.y, W.y, ac1);
                acc = fmaf(H.z, W.z, acc);
                ac1 = fmaf(H.w, W.w, ac1);
            }
            xs[xv][xc] = fmaxf(acc + ac1, 0.0f);
        }
        if (tid < VB) {
            const int ov = tid;
            const int vg = vbase0 + ov;
            CP_WAIT0();                        // raw(t+1) landed
            float spd = s_spd[ov];             // spd(t): C(t) updates only after bar2
            pos = fmaf(0.1f, spd, pos);        // pos(t+1) = reference pos output at t
            out[OUT_POS + (size_t)vg * NT + t] = pos;
            const float4* rw = (const float4*)&raws[(t + 1) & 1][ov][0];
            float4 r0 = rw[0], r1 = rw[1], r2 = rw[2];
            float* cb = &xin[tb ^ 1][ov][0];   // cur floats [0..11]; x-threads read [12..31]
            const float ih = 0.01f, iv = 0.025f;
            cb[0]  = nanfix((r0.x - pos) * ih);
            cb[1]  = nanfix((r0.y - pos) * ih);
            cb[2]  = nanfix((r0.z - pos) * ih);
            cb[3]  = nanfix((pos - r0.w) * ih);
            cb[4]  = nanfix((pos - r1.x) * ih);
            cb[5]  = nanfix((pos - r1.y) * ih);
            cb[6]  = nanfix(r1.z * iv);
            cb[7]  = nanfix(r1.w * iv);
            cb[8]  = nanfix(r2.x * iv);
            cb[9]  = nanfix(r2.y * iv);
            cb[10] = nanfix(r2.z * iv);
            cb[11] = nanfix(r2.w * iv);
            if (t + 2 < NT) {                  // prefetch raw(t+2)
                uint32_t d = (uint32_t)__cvta_generic_to_shared(&raws[t & 1][ov][0]);
                const float* src = inp + ((size_t)vg * NT + (t + 2)) * 12;
                cpasync16(d, src); cpasync16(d + 16, src + 4); cpasync16(d + 32, src + 8);
                CP_COMMIT();
            }
        }
        __syncthreads();   // barrier 2: xs + cur(t+1) visible

        // ---- Phase C: lc / acc / spd update (64 thr; no trailing barrier) ----
        if (tid < 4 * VB) {
            const int cv = tid >> 2, cq = tid & 3;
            const int vg = vbase0 + cv;
            float acc = s_headb[cq];
#pragma unroll
            for (int m = 0; m < 10; m++) acc = fmaf(xs[cv][m], s_head[m][cq], acc);
            if (cq < 3) {
                out[OUT_LC + ((size_t)vg * NT + t) * 3 + cq] = acc;
            } else {
                float a = fmaf(10.0f, acc, -6.0f);
                s_spd[cv] = fmaf(0.1f, a, s_spd[cv]);
            }
        }
        // C(t) reads xs / writes s_spd; B(t+1) writes xs / reads s_spd — ordered
        // by barrier 1 of step t+1. A(t+1) touches only xin buffers, disjoint.
    }

    __syncthreads();
    // ---- finals ----
    if (tid < VB) out[OUT_SPD + vbase0 + tid] = s_spd[tid];
    for (int i = tid; i < VB * UNITS; i += THREADS) {
        int v = i / UNITS, uu = i % UNITS;
        out[OUT_H + (size_t)(vbase0 + v) * UNITS + uu] = xin[NT & 1][v][12 + uu];
    }
    if (p == 0) {
#pragma unroll
        for (int vi = 0; vi < 4; vi++)
            out[OUT_C + (size_t)(vbase0 + v0 + vi) * UNITS + u] = c2[vi];
    }
}

extern "C" void kernel_launch(void* const* d_in, const int* in_sizes, int n_in,
                              void* d_out, int out_size) {
    const float* inp        = (const float*)d_in[0];
    const float* init_state = (const float*)d_in[1];
    const float* h0         = (const float*)d_in[2];
    const float* c0         = (const float*)d_in[3];
    const float* Wk         = (const float*)d_in[4];
    const float* Wr         = (const float*)d_in[5];
    const float* bzv        = (const float*)d_in[6];
    const float* d2w        = (const float*)d_in[7];
    const float* d2b        = (const float*)d_in[8];
    const float* lcw        = (const float*)d_in[9];
    const float* lcb        = (const float*)d_in[10];
    const float* d1w        = (const float*)d_in[11];
    const float* d1b        = (const float*)d_in[12];
    float* out = (float*)d_out;

    rnncf_kernel<<<BLOCKS, THREADS>>>(inp, init_state, h0, c0, Wk, Wr, bzv,
                                      d2w, d2b, lcw, lcb, d1w, d1b, out);
}

// round 8
// speedup vs baseline: 1.7173x; 1.0597x over previous
#include <cuda_runtime.h>
#include <cstdint>

#define NV     8192
#define NT     1000
#define UNITS  20
#define IND    12
#define NCOL   80
#define VB     16           // vehicles per block
#define XSTR   36           // padded xin stride (floats): 144B -> 4-bank shift/vehicle
#define THREADS 160         // 4 groups of 40 threads; group serves 4 vehicles
#define BLOCKS (NV/VB)      // 512  -> one residency wave

// output packing (flat concat in reference return order)
#define OUT_POS 0
#define OUT_LC  (NV*NT)
#define OUT_SPD (OUT_LC + NV*NT*3)
#define OUT_H   (OUT_SPD + NV)
#define OUT_C   (OUT_H + NV*UNITS)

typedef unsigned long long ull;

__device__ __forceinline__ ull pk(float x, float y) {
    ull r; asm("mov.b64 %0, {%1,%2};" : "=l"(r) : "f"(x), "f"(y)); return r;
}
__device__ __forceinline__ float2 unpk(ull v) {
    float2 f; asm("mov.b64 {%0,%1}, %2;" : "=f"(f.x), "=f"(f.y) : "l"(v)); return f;
}
__device__ __forceinline__ void ffma2(ull& d, ull a, ull b) {
    asm("fma.rn.f32x2 %0, %1, %2, %0;" : "+l"(d) : "l"(a), "l"(b));
}
__device__ __forceinline__ ull add2(ull a, ull b) {
    ull r; asm("add.rn.f32x2 %0, %1, %2;" : "=l"(r) : "l"(a), "l"(b)); return r;
}
__device__ __forceinline__ void lds2u64(ull& a, ull& b, uint32_t addr) {
    asm volatile("ld.shared.v2.u64 {%0,%1}, [%2];" : "=l"(a), "=l"(b) : "r"(addr));
}
__device__ __forceinline__ ull lds64(uint32_t addr) {
    ull r; asm volatile("ld.shared.b64 %0, [%1];" : "=l"(r) : "r"(addr)); return r;
}
__device__ __forceinline__ float sigf(float x) {
    return __fdividef(1.0f, 1.0f + __expf(-x));
}
__device__ __forceinline__ float tanh_ex(float x) {
    return fmaf(2.0f, sigf(2.0f * x), -1.0f);
}
__device__ __forceinline__ float nanfix(float v) { return (v == v) ? v : 1.0f; }

__device__ __forceinline__ void cpasync16(uint32_t dst, const void* src) {
    asm volatile("cp.async.cg.shared.global [%0], [%1], 16;" :: "r"(dst), "l"(src));
}
#define CP_COMMIT() asm volatile("cp.async.commit_group;")
#define CP_WAIT0()  asm volatile("cp.async.wait_group 0;")

__global__ void __launch_bounds__(THREADS, 4)
rnncf_kernel(const float* __restrict__ inp,        // (NV, NT, 12)
             const float* __restrict__ init_state, // (NV, 2)
             const float* __restrict__ h0,         // (NV, 20)
             const float* __restrict__ c0,         // (NV, 20)
             const float* __restrict__ Wk,         // (12, 80)
             const float* __restrict__ Wr,         // (20, 80)
             const float* __restrict__ bz,         // (80)
             const float* __restrict__ d2w,        // (20, 10)
             const float* __restrict__ d2b,        // (10)
             const float* __restrict__ lcw,        // (10, 3)
             const float* __restrict__ lcb,        // (3)
             const float* __restrict__ d1w,        // (10, 1)
             const float* __restrict__ d1b,        // (1)
             float* __restrict__ out)
{
    // xin[buf][v][0..11]=cur, [12..31]=h, [32..35]=pad (bank de-conflict)
    __shared__ __align__(16) float xin[2][VB][XSTR];
    __shared__ __align__(16) float raws[2][VB][12];
    __shared__ float xs[VB][12];
    __shared__ float s_spd[VB];
    __shared__ __align__(16) ull s_d2p[10][10];  // [q][xc] = (d2w[2q][xc], d2w[2q+1][xc])
    __shared__ float s_d2b[10];
    __shared__ float s_head[10][4];       // [m][q]: q<3 -> lcw col q, q=3 -> d1w
    __shared__ float s_headb[4];

    const int tid  = threadIdx.x;
    const int grpv = tid / 40;          // group 0..3, serves 4 vehicles
    const int r    = tid % 40;
    const int u    = r >> 1;            // unit 0..19
    const int p    = r & 1;             // 0 -> (i,f) columns, 1 -> (g,o) columns
    const int v0   = grpv * 4;
    const int vbase0 = blockIdx.x * VB;

    // ---- static head weights -> smem ----
    if (tid < 100) {
        int q = tid / 10, c = tid % 10;
        s_d2p[q][c] = pk(d2w[(2 * q) * 10 + c], d2w[(2 * q + 1) * 10 + c]);
    }
    if (tid < 10) s_d2b[tid] = d2b[tid];
    if (tid < 40) { int m = tid >> 2, q = tid & 3; s_head[m][q] = (q < 3) ? lcw[m * 3 + q] : d1w[m]; }
    if (tid < 4)  s_headb[tid] = (tid < 3) ? lcb[tid] : d1b[0];

    // ---- branchless activation constants (for column A) ----
    const float kA = p ? 2.0f : 1.0f;   // actA = fmaf(mA, sigf(kA*z), cA)
    const float mA = p ? 2.0f : 1.0f;   // p=0: sigmoid(z_i); p=1: tanh(z_g)
    const float cA = p ? -1.0f : 0.0f;

    // ---- register-resident weights: two columns, packed across k ----
    const int colA = p ? (40 + u) : u;          // g or i
    const int colB = p ? (60 + u) : (20 + u);   // o or f
    ull wA[16], wB[16];
#pragma unroll
    for (int q = 0; q < 16; q++) {
        int k0 = 2 * q, k1 = 2 * q + 1;
        float a0 = (k0 < IND) ? Wk[k0 * NCOL + colA] : Wr[(k0 - IND) * NCOL + colA];
        float a1 = (k1 < IND) ? Wk[k1 * NCOL + colA] : Wr[(k1 - IND) * NCOL + colA];
        wA[q] = pk(a0, a1);
        float b0 = (k0 < IND) ? Wk[k0 * NCOL + colB] : Wr[(k0 - IND) * NCOL + colB];
        float b1 = (k1 < IND) ? Wk[k1 * NCOL + colB] : Wr[(k1 - IND) * NCOL + colB];
        wB[q] = pk(b0, b1);
    }
    const float bzA = bz[colA], bzB = bz[colB];
    const ull zero2 = pk(0.0f, 0.0f);

    // ---- state init ----
    float c2[4];
#pragma unroll
    for (int vi = 0; vi < 4; vi++)
        c2[vi] = c0[(vbase0 + v0 + vi) * UNITS + u];
    float pos = 0.0f;

    for (int i = tid; i < VB * UNITS; i += THREADS) {   // h0 -> xin[0]
        int v = i / UNITS, uu = i % UNITS;
        xin[0][v][12 + uu] = h0[(vbase0 + v) * UNITS + uu];
    }
    if (tid < VB) {                     // vehicle owners: tid = vehicle index
        const int ov = tid;
        const int vg = vbase0 + ov;
        pos = init_state[vg * 2 + 0];
        s_spd[ov] = init_state[vg * 2 + 1];
        const float4* ip = (const float4*)(inp + (size_t)vg * NT * 12);
        float4 r0 = ip[0], r1 = ip[1], r2 = ip[2];
        float* cb = &xin[0][ov][0];
        const float ih = 0.01f, iv = 0.025f;
        cb[0]  = nanfix((r0.x - pos) * ih);
        cb[1]  = nanfix((r0.y - pos) * ih);
        cb[2]  = nanfix((r0.z - pos) * ih);
        cb[3]  = nanfix((pos - r0.w) * ih);
        cb[4]  = nanfix((pos - r1.x) * ih);
        cb[5]  = nanfix((pos - r1.y) * ih);
        cb[6]  = nanfix(r1.z * iv);
        cb[7]  = nanfix(r1.w * iv);
        cb[8]  = nanfix(r2.x * iv);
        cb[9]  = nanfix(r2.y * iv);
        cb[10] = nanfix(r2.z * iv);
        cb[11] = nanfix(r2.w * iv);
        uint32_t d = (uint32_t)__cvta_generic_to_shared(&raws[1][ov][0]);
        const float* src = inp + ((size_t)vg * NT + 1) * 12;
        cpasync16(d, src); cpasync16(d + 16, src + 4); cpasync16(d + 32, src + 8);
        CP_COMMIT();
    }
    __syncthreads();

    for (int t = 0; t < NT; t++) {
        const int tb = t & 1;

        // ---- Phase A: LSTM matvec + gates + cell, 4 vehicles (all 160 thr) ----
#pragma unroll
        for (int vi = 0; vi < 4; vi++) {
            const int v = v0 + vi;
            uint32_t xb = (uint32_t)__cvta_generic_to_shared(&xin[tb][v][0]);
            ull aA0 = pk(bzA, 0.0f), aA1 = zero2;
            ull aB0 = pk(bzB, 0.0f), aB1 = zero2;
#pragma unroll
            for (int q = 0; q < 8; q++) {       // 16B of x feeds 4 FFMA2
                ull xa, xc;
                lds2u64(xa, xc, xb + q * 16);
                ffma2(aA0, xa, wA[2 * q]);
                ffma2(aB0, xa, wB[2 * q]);
                ffma2(aA1, xc, wA[2 * q + 1]);
                ffma2(aB1, xc, wB[2 * q + 1]);
            }
            float2 fA = unpk(add2(aA0, aA1));
            float2 fB = unpk(add2(aB0, aB1));
            float zA = fA.x + fA.y;
            float zB = fB.x + fB.y;
            float actA = fmaf(mA, sigf(kA * zA), cA);  // p0: sig(i); p1: tanh(g)
            float actB = sigf(zB);                     // p0: sig(f); p1: sig(o)
            float oa = __shfl_xor_sync(0xFFFFFFFFu, actA, 1);  // partner's A
            float ob = __shfl_xor_sync(0xFFFFFFFFu, actB, 1);  // partner's B
            if (p == 0) {   // p0 holds: si=actA, sf=actB, tg=oa, so=ob
                float cc = fmaf(actB, c2[vi], actA * oa);
                c2[vi] = cc;
                xin[tb ^ 1][v][12 + u] = ob * tanh_ex(cc);
            }
        }
        __syncthreads();   // barrier 1: h(t) visible

        // ---- Phase B: head-x in f32x2 (all 160 thr) + owner work (16 thr) ----
        {
            const int xv = tid / 10, xc = tid % 10;       // 16 veh x 10 cols = 160
            uint32_t hb = (uint32_t)__cvta_generic_to_shared(&xin[tb ^ 1][xv][12]);
            uint32_t wb = (uint32_t)__cvta_generic_to_shared(&s_d2p[0][xc]);
            ull a0 = pk(s_d2b[xc], 0.0f), a1 = zero2;
#pragma unroll
            for (int m = 0; m < 5; m++) {       // h pairs feed FFMA2 directly
                ull ha, hc;
                lds2u64(ha, hc, hb + m * 16);
                ffma2(a0, ha, lds64(wb + (2 * m) * 80));
                ffma2(a1, hc, lds64(wb + (2 * m + 1) * 80));
            }
            float2 f = unpk(add2(a0, a1));
            xs[xv][xc] = fmaxf(f.x + f.y, 0.0f);
        }
        if (tid < VB) {
            const int ov = tid;
            const int vg = vbase0 + ov;
            CP_WAIT0();                        // raw(t+1) landed
            float spd = s_spd[ov];             // spd(t): C(t) updates only after bar2
            pos = fmaf(0.1f, spd, pos);        // pos(t+1) = reference pos output at t
            out[OUT_POS + (size_t)vg * NT + t] = pos;
            const float4* rw = (const float4*)&raws[(t + 1) & 1][ov][0];
            float4 r0 = rw[0], r1 = rw[1], r2 = rw[2];
            float* cb = &xin[tb ^ 1][ov][0];   // cur floats [0..11]
            const float ih = 0.01f, iv = 0.025f;
            cb[0]  = nanfix((r0.x - pos) * ih);
            cb[1]  = nanfix((r0.y - pos) * ih);
            cb[2]  = nanfix((r0.z - pos) * ih);
            cb[3]  = nanfix((pos - r0.w) * ih);
            cb[4]  = nanfix((pos - r1.x) * ih);
            cb[5]  = nanfix((pos - r1.y) * ih);
            cb[6]  = nanfix(r1.z * iv);
            cb[7]  = nanfix(r1.w * iv);
            cb[8]  = nanfix(r2.x * iv);
            cb[9]  = nanfix(r2.y * iv);
            cb[10] = nanfix(r2.z * iv);
            cb[11] = nanfix(r2.w * iv);
            if (t + 2 < NT) {                  // prefetch raw(t+2)
                uint32_t d = (uint32_t)__cvta_generic_to_shared(&raws[t & 1][ov][0]);
                const float* src = inp + ((size_t)vg * NT + (t + 2)) * 12;
                cpasync16(d, src); cpasync16(d + 16, src + 4); cpasync16(d + 32, src + 8);
                CP_COMMIT();
            }
        }
        __syncthreads();   // barrier 2: xs + cur(t+1) visible

        // ---- Phase C: lc / acc / spd update (64 thr; no trailing barrier) ----
        if (tid < 4 * VB) {
            const int cv = tid >> 2, cq = tid & 3;
            const int vg = vbase0 + cv;
            float acc = s_headb[cq];
#pragma unroll
            for (int m = 0; m < 10; m++) acc = fmaf(xs[cv][m], s_head[m][cq], acc);
            if (cq < 3) {
                out[OUT_LC + ((size_t)vg * NT + t) * 3 + cq] = acc;
            } else {
                float a = fmaf(10.0f, acc, -6.0f);
                s_spd[cv] = fmaf(0.1f, a, s_spd[cv]);
            }
        }
        // C(t) reads xs / writes s_spd; B(t+1) writes xs / reads s_spd — ordered
        // by barrier 1 of step t+1. A(t+1) touches only xin buffers, disjoint.
    }

    __syncthreads();
    // ---- finals ----
    if (tid < VB) out[OUT_SPD + vbase0 + tid] = s_spd[tid];
    for (int i = tid; i < VB * UNITS; i += THREADS) {
        int v = i / UNITS, uu = i % UNITS;
        out[OUT_H + (size_t)(vbase0 + v) * UNITS + uu] = xin[NT & 1][v][12 + uu];
    }
    if (p == 0) {
#pragma unroll
        for (int vi = 0; vi < 4; vi++)
            out[OUT_C + (size_t)(vbase0 + v0 + vi) * UNITS + u] = c2[vi];
    }
}

extern "C" void kernel_launch(void* const* d_in, const int* in_sizes, int n_in,
                              void* d_out, int out_size) {
    const float* inp        = (const float*)d_in[0];
    const float* init_state = (const float*)d_in[1];
    const float* h0         = (const float*)d_in[2];
    const float* c0         = (const float*)d_in[3];
    const float* Wk         = (const float*)d_in[4];
    const float* Wr         = (const float*)d_in[5];
    const float* bzv        = (const float*)d_in[6];
    const float* d2w        = (const float*)d_in[7];
    const float* d2b        = (const float*)d_in[8];
    const float* lcw        = (const float*)d_in[9];
    const float* lcb        = (const float*)d_in[10];
    const float* d1w        = (const float*)d_in[11];
    const float* d1b        = (const float*)d_in[12];
    float* out = (float*)d_out;

    rnncf_kernel<<<BLOCKS, THREADS>>>(inp, init_state, h0, c0, Wk, Wr, bzv,
                                      d2w, d2b, lcw, lcb, d1w, d1b, out);
}